// round 2
// baseline (speedup 1.0000x reference)
#include <cuda_runtime.h>
#include <cstdint>
#include <cstddef>

// ---------------- problem constants ----------------
#define NUM_HEADS 8
#define DHEAD 32
#define BLOCK_SZ 8
#define HALO 3
#define WIN 14          // BLOCK + 2*HALO
#define WINP 196        // WIN*WIN
#define NHB 12          // 96/8
#define NB 144          // 12*12
#define HW 96
#define SPATIAL 9216    // 96*96
#define BATCH 8
#define CIN 256
#define OQKV 768        // 256 q + 512 kv
#define SCALE 0.17677669529663687f

typedef unsigned long long u64;

// ---- f32x2 packed-math helpers (Blackwell dual-rate fp32) ----
__device__ __forceinline__ u64 pack2(float lo, float hi) {
    u64 r; asm("mov.b64 %0, {%1, %2};" : "=l"(r) : "f"(lo), "f"(hi)); return r;
}
__device__ __forceinline__ void unpack2(u64 v, float& lo, float& hi) {
    asm("mov.b64 {%0, %1}, %2;" : "=f"(lo), "=f"(hi) : "l"(v));
}
__device__ __forceinline__ void fma2(u64& d, u64 a, u64 b) {
    asm("fma.rn.f32x2 %0, %1, %2, %0;" : "+l"(d) : "l"(a), "l"(b));
}
__device__ __forceinline__ void mul2(u64& d, u64 a) {
    asm("mul.rn.f32x2 %0, %0, %1;" : "+l"(d) : "l"(a));
}
__device__ __forceinline__ u64 add2(u64 a, u64 b) {
    u64 r; asm("add.rn.f32x2 %0, %1, %2;" : "=l"(r) : "l"(a), "l"(b)); return r;
}

// scratch: qkv[b][o][s], o<256 -> q (head*32+d), o>=256 -> kv (256 + head*64 + c)
__device__ float g_qkv[(size_t)BATCH * OQKV * SPATIAL];

// ---------------- kernel 1: fused QKV projection GEMM ----------------
// C[b][o][s] = sum_c W[o][c] * x[b][c][s]
// tile 128x128, BK=16, 256 threads, 8x8 micro-tile, FFMA2 inner product.
#define GBM 128
#define GBN 128
#define GBK 16
#define APAD 132   // As row stride (words); multiple of 4 for LDS.128 alignment

__global__ void __launch_bounds__(256, 2) qkv_gemm(
    const float* __restrict__ x,
    const float* __restrict__ qw,
    const float* __restrict__ kvw)
{
    __shared__ float As[GBK][APAD];   // [k][m]
    __shared__ float Bs[GBK][GBN];    // [k][n]

    const int b  = blockIdx.z;
    const int m0 = blockIdx.y * GBM;
    const int n0 = blockIdx.x * GBN;
    const int tid = threadIdx.x;

    const float* xb = x + (size_t)b * CIN * SPATIAL;

    const int tr = tid >> 4;          // 0..15 : rows tr*8 .. +7
    const int tc = tid & 15;          // 0..15 : cols tc*8 .. +7

    // A staging: idx = tid + i*256 -> row = idx>>2 (0..127), ck = (idx&3)*4
    // B staging: idx = tid + i*256 -> krow = idx>>5 (0..15), col = (idx&31)*4
    const int a_row0 = tid >> 2;
    const int a_ck   = (tid & 3) * 4;
    const int b_kr0  = tid >> 5;
    const int b_col  = (tid & 31) * 4;

    // global row pointers for the two A loads (rows a_row0, a_row0+64)
    const float* wrowp[2];
#pragma unroll
    for (int i = 0; i < 2; i++) {
        const int o = m0 + a_row0 + i * 64;
        wrowp[i] = (o < 256) ? (qw + (size_t)o * CIN) : (kvw + (size_t)(o - 256) * CIN);
    }

    u64 acc2[4][8];
#pragma unroll
    for (int i = 0; i < 4; i++)
#pragma unroll
        for (int j = 0; j < 8; j++) acc2[i][j] = 0ULL;

    float4 pa[2], pb[2];
    // prefetch tile 0
#pragma unroll
    for (int i = 0; i < 2; i++) {
        pa[i] = *(const float4*)(wrowp[i] + 0 + a_ck);
        pb[i] = *(const float4*)(xb + (size_t)(0 + b_kr0 + i * 8) * SPATIAL + n0 + b_col);
    }

    for (int k0 = 0; k0 < CIN; k0 += GBK) {
        // commit staged regs to smem
#pragma unroll
        for (int i = 0; i < 2; i++) {
            const int ar = a_row0 + i * 64;
            As[a_ck + 0][ar] = pa[i].x;
            As[a_ck + 1][ar] = pa[i].y;
            As[a_ck + 2][ar] = pa[i].z;
            As[a_ck + 3][ar] = pa[i].w;
            *(float4*)&Bs[b_kr0 + i * 8][b_col] = pb[i];
        }
        __syncthreads();

        if (k0 + GBK < CIN) {
#pragma unroll
            for (int i = 0; i < 2; i++) {
                pa[i] = *(const float4*)(wrowp[i] + k0 + GBK + a_ck);
                pb[i] = *(const float4*)(xb + (size_t)(k0 + GBK + b_kr0 + i * 8) * SPATIAL + n0 + b_col);
            }
        }

#pragma unroll
        for (int k = 0; k < GBK; k++) {
            ulonglong2 a01 = *(const ulonglong2*)&As[k][tr * 8];
            ulonglong2 a23 = *(const ulonglong2*)&As[k][tr * 8 + 4];
            u64 a2[4] = {a01.x, a01.y, a23.x, a23.y};
            float4 b0 = *(const float4*)&Bs[k][tc * 8];
            float4 b1 = *(const float4*)&Bs[k][tc * 8 + 4];
            u64 bd[8];
            bd[0] = pack2(b0.x, b0.x); bd[1] = pack2(b0.y, b0.y);
            bd[2] = pack2(b0.z, b0.z); bd[3] = pack2(b0.w, b0.w);
            bd[4] = pack2(b1.x, b1.x); bd[5] = pack2(b1.y, b1.y);
            bd[6] = pack2(b1.z, b1.z); bd[7] = pack2(b1.w, b1.w);
#pragma unroll
            for (int i = 0; i < 4; i++)
#pragma unroll
                for (int j = 0; j < 8; j++)
                    fma2(acc2[i][j], a2[i], bd[j]);
        }
        __syncthreads();
    }

    float* outb = g_qkv + (size_t)b * OQKV * SPATIAL;
#pragma unroll
    for (int i = 0; i < 4; i++) {
        float lo[8], hi[8];
#pragma unroll
        for (int j = 0; j < 8; j++) unpack2(acc2[i][j], lo[j], hi[j]);
        const int r0 = m0 + tr * 8 + 2 * i;
        float* p0 = outb + (size_t)r0 * SPATIAL + n0 + tc * 8;
        float* p1 = p0 + SPATIAL;
        *(float4*)(p0)     = make_float4(lo[0], lo[1], lo[2], lo[3]);
        *(float4*)(p0 + 4) = make_float4(lo[4], lo[5], lo[6], lo[7]);
        *(float4*)(p1)     = make_float4(hi[0], hi[1], hi[2], hi[3]);
        *(float4*)(p1 + 4) = make_float4(hi[4], hi[5], hi[6], hi[7]);
    }
}

// ---------------- kernel 2: halo attention ----------------
// grid (144, 64), 128 threads.
// thread t: qp = t>>2 (queries qp and qp+32), quad = t&3 -> 7x7 quadrant of
// the 14x14 window (yhalf = quad>>1, xhalf = quad&1). Flash online softmax,
// 4 partials combined by lane shuffles (xor 1, xor 2).
#define KV_STRIDE 68                         // 64 ch + pad
#define SMEM_KV   (WINP * KV_STRIDE)         // 13328 floats
#define RELSTRIDE 36                         // rel table row stride (16B-aligned)
#define SMEM_REL  (27 * RELSTRIDE)           // 972 floats each
#define SMEM_FLOATS (SMEM_KV + 2 * SMEM_REL)
#define SMEM_BYTES  (SMEM_FLOATS * 4)

__global__ void __launch_bounds__(128) halo_attn(
    const float* __restrict__ hrel,
    const float* __restrict__ wrel,
    float* __restrict__ out)
{
    extern __shared__ float smem[];
    float* sKV = smem;                       // [196][68] : c<32 K, c>=32 V
    float* sH  = smem + SMEM_KV;             // [27][36]
    float* sW  = sH + SMEM_REL;              // [27][36]

    const int tid = threadIdx.x;
    const int nbidx = blockIdx.x;            // 0..143
    const int bh = blockIdx.y;               // 0..63
    const int b = bh >> 3, head = bh & 7;
    const int by = nbidx / NHB, bx = nbidx % NHB;

    // ---- stage rel tables ----
    for (int idx = tid; idx < 27 * 32; idx += 128) {
        const int r = idx >> 5, d = idx & 31;
        sH[r * RELSTRIDE + d] = hrel[idx];
        sW[r * RELSTRIDE + d] = wrel[idx];
    }

    // ---- stage KV window (global c-major -> shared pos-major) ----
    const float* kvbase = g_qkv + ((size_t)b * OQKV + 256 + head * 64) * SPATIAL;
    for (int idx = tid; idx < 64 * WINP; idx += 128) {
        const int c = idx / WINP, p = idx % WINP;
        const int y = p / WIN, xx = p % WIN;
        const int gh = by * BLOCK_SZ + y - HALO;
        const int gw = bx * BLOCK_SZ + xx - HALO;
        float v = 0.f;
        if ((unsigned)gh < (unsigned)HW && (unsigned)gw < (unsigned)HW)
            v = kvbase[(size_t)c * SPATIAL + gh * HW + gw];
        sKV[p * KV_STRIDE + c] = v;
    }

    // ---- per-thread work assignment ----
    const int qp   = tid >> 2;               // 0..31
    const int quad = tid & 3;
    const int y0 = (quad >> 1) * 7;
    const int x0 = (quad & 1) * 7;

    const int qiA = qp >> 3;                  // 0..3
    const int qj  = qp & 7;
    const int qiB = qiA + 4;

    const int spA = (by * BLOCK_SZ + qiA) * HW + bx * BLOCK_SZ + qj;
    const int spB = (by * BLOCK_SZ + qiB) * HW + bx * BLOCK_SZ + qj;

    // ---- load both Q rows as f32x2 d-pairs ----
    const float* qbA = g_qkv + ((size_t)b * OQKV + head * DHEAD) * SPATIAL + spA;
    const float* qbB = qbA + (spB - spA);

    u64 qa2[16], qb2[16];
#pragma unroll
    for (int dd = 0; dd < 16; dd++) {
        qa2[dd] = pack2(qbA[(size_t)(2 * dd) * SPATIAL], qbA[(size_t)(2 * dd + 1) * SPATIAL]);
        qb2[dd] = pack2(qbB[(size_t)(2 * dd) * SPATIAL], qbB[(size_t)(2 * dd + 1) * SPATIAL]);
    }

    __syncthreads();

    // ---- relative-position terms (unscaled q) ----
    float rwA[7], rwB[7], rhA[7], rhB[7];
#pragma unroll
    for (int i = 0; i < 7; i++) {
        {   // width rel, row 13 + (x0+i) - qj
            const ulonglong2* wr = (const ulonglong2*)&sW[(13 + x0 + i - qj) * RELSTRIDE];
            u64 s0 = 0ULL, s1 = 0ULL;
#pragma unroll
            for (int m = 0; m < 4; m++) {
                ulonglong2 wv = wr[m];
                fma2(s0, qa2[2 * m] , wv.x);
                fma2(s1, qa2[2 * m + 1], wv.y);
            }
#pragma unroll
            for (int m = 4; m < 8; m++) {
                ulonglong2 wv = wr[m];
                fma2(s0, qa2[2 * m], wv.x);
                fma2(s1, qa2[2 * m + 1], wv.y);
            }
            float l0, h0; unpack2(add2(s0, s1), l0, h0);
            rwA[i] = l0 + h0;
            s0 = 0ULL; s1 = 0ULL;
#pragma unroll
            for (int m = 0; m < 8; m++) {
                ulonglong2 wv = wr[m];
                fma2(s0, qb2[2 * m], wv.x);
                fma2(s1, qb2[2 * m + 1], wv.y);
            }
            unpack2(add2(s0, s1), l0, h0);
            rwB[i] = l0 + h0;
        }
        {   // height rel
            const ulonglong2* hrA = (const ulonglong2*)&sH[(13 + y0 + i - qiA) * RELSTRIDE];
            const ulonglong2* hrB = (const ulonglong2*)&sH[(13 + y0 + i - qiB) * RELSTRIDE];
            u64 s0 = 0ULL, s1 = 0ULL;
#pragma unroll
            for (int m = 0; m < 8; m++) {
                ulonglong2 hv = hrA[m];
                fma2(s0, qa2[2 * m], hv.x);
                fma2(s1, qa2[2 * m + 1], hv.y);
            }
            float l0, h0; unpack2(add2(s0, s1), l0, h0);
            rhA[i] = l0 + h0;
            s0 = 0ULL; s1 = 0ULL;
#pragma unroll
            for (int m = 0; m < 8; m++) {
                ulonglong2 hv = hrB[m];
                fma2(s0, qb2[2 * m], hv.x);
                fma2(s1, qb2[2 * m + 1], hv.y);
            }
            unpack2(add2(s0, s1), l0, h0);
            rhB[i] = l0 + h0;
        }
    }

    // fold QK scale into q
    const u64 sc2 = pack2(SCALE, SCALE);
#pragma unroll
    for (int dd = 0; dd < 16; dd++) { mul2(qa2[dd], sc2); mul2(qb2[dd], sc2); }

    // ---- flash loop over the 7x7 quadrant ----
    float mA = -1e30f, lA = 0.f, mB = -1e30f, lB = 0.f;
    u64 accA[16], accB[16];
#pragma unroll
    for (int dd = 0; dd < 16; dd++) { accA[dd] = 0ULL; accB[dd] = 0ULL; }

    for (int yy = 0; yy < 7; yy++) {
        const int prow = (y0 + yy) * WIN + x0;
        const float rhvA = rhA[yy], rhvB = rhB[yy];
        float lgA[7], lgB[7];
        float rmA = -1e30f, rmB = -1e30f;
#pragma unroll
        for (int xx = 0; xx < 7; xx++) {
            const ulonglong2* kp = (const ulonglong2*)(sKV + (prow + xx) * KV_STRIDE);
            u64 sA0 = 0ULL, sA1 = 0ULL, sB0 = 0ULL, sB1 = 0ULL;
#pragma unroll
            for (int m = 0; m < 8; m++) {
                ulonglong2 kv = kp[m];
                fma2(sA0, qa2[2 * m],     kv.x);
                fma2(sA1, qa2[2 * m + 1], kv.y);
                fma2(sB0, qb2[2 * m],     kv.x);
                fma2(sB1, qb2[2 * m + 1], kv.y);
            }
            float l0, h0;
            unpack2(add2(sA0, sA1), l0, h0);
            const float sA = l0 + h0 + rhvA + rwA[xx];
            unpack2(add2(sB0, sB1), l0, h0);
            const float sB = l0 + h0 + rhvB + rwB[xx];
            lgA[xx] = sA; rmA = fmaxf(rmA, sA);
            lgB[xx] = sB; rmB = fmaxf(rmB, sB);
        }
        const float mnA = fmaxf(mA, rmA);
        const float mnB = fmaxf(mB, rmB);
        const float cA = __expf(mA - mnA);
        const float cB = __expf(mB - mnB);
        lA *= cA; lB *= cB;
        const u64 cA2 = pack2(cA, cA), cB2 = pack2(cB, cB);
#pragma unroll
        for (int dd = 0; dd < 16; dd++) { mul2(accA[dd], cA2); mul2(accB[dd], cB2); }
        mA = mnA; mB = mnB;
#pragma unroll
        for (int xx = 0; xx < 7; xx++) {
            const float pA = __expf(lgA[xx] - mA);
            const float pB = __expf(lgB[xx] - mB);
            lA += pA; lB += pB;
            const u64 pA2 = pack2(pA, pA), pB2 = pack2(pB, pB);
            const ulonglong2* vp = (const ulonglong2*)(sKV + (prow + xx) * KV_STRIDE + 32);
#pragma unroll
            for (int m = 0; m < 8; m++) {
                ulonglong2 vv = vp[m];
                fma2(accA[2 * m],     pA2, vv.x);
                fma2(accA[2 * m + 1], pA2, vv.y);
                fma2(accB[2 * m],     pB2, vv.x);
                fma2(accB[2 * m + 1], pB2, vv.y);
            }
        }
    }

    // ---- combine 4 quadrant partials via lane shuffles ----
    const unsigned FULL = 0xFFFFFFFFu;
    float* obA = out + ((size_t)b * 256 + head * DHEAD) * SPATIAL + spA;
    float* obB = obA + (spB - spA);

    {
        float M = mA;
        M = fmaxf(M, __shfl_xor_sync(FULL, M, 1));
        M = fmaxf(M, __shfl_xor_sync(FULL, M, 2));
        const float w = __expf(mA - M);
        float lw = lA * w;
        lw += __shfl_xor_sync(FULL, lw, 1);
        lw += __shfl_xor_sync(FULL, lw, 2);
        const float inv = 1.f / lw;
#pragma unroll
        for (int dd = 0; dd < 16; dd++) {
            float f0, f1; unpack2(accA[dd], f0, f1);
            f0 *= w; f1 *= w;
            f0 += __shfl_xor_sync(FULL, f0, 1);
            f0 += __shfl_xor_sync(FULL, f0, 2);
            f1 += __shfl_xor_sync(FULL, f1, 1);
            f1 += __shfl_xor_sync(FULL, f1, 2);
            if (quad == 0) {
                obA[(size_t)(2 * dd) * SPATIAL]     = f0 * inv;
                obA[(size_t)(2 * dd + 1) * SPATIAL] = f1 * inv;
            }
        }
    }
    {
        float M = mB;
        M = fmaxf(M, __shfl_xor_sync(FULL, M, 1));
        M = fmaxf(M, __shfl_xor_sync(FULL, M, 2));
        const float w = __expf(mB - M);
        float lw = lB * w;
        lw += __shfl_xor_sync(FULL, lw, 1);
        lw += __shfl_xor_sync(FULL, lw, 2);
        const float inv = 1.f / lw;
#pragma unroll
        for (int dd = 0; dd < 16; dd++) {
            float f0, f1; unpack2(accB[dd], f0, f1);
            f0 *= w; f1 *= w;
            f0 += __shfl_xor_sync(FULL, f0, 1);
            f0 += __shfl_xor_sync(FULL, f0, 2);
            f1 += __shfl_xor_sync(FULL, f1, 1);
            f1 += __shfl_xor_sync(FULL, f1, 2);
            if (quad == 0) {
                obB[(size_t)(2 * dd) * SPATIAL]     = f0 * inv;
                obB[(size_t)(2 * dd + 1) * SPATIAL] = f1 * inv;
            }
        }
    }
}

// ---------------- launch ----------------
extern "C" void kernel_launch(void* const* d_in, const int* in_sizes, int n_in,
                              void* d_out, int out_size)
{
    const float* x    = (const float*)d_in[0];
    const float* qw   = (const float*)d_in[1];
    const float* kvw  = (const float*)d_in[2];
    const float* hrel = (const float*)d_in[3];
    const float* wrel = (const float*)d_in[4];
    float* out = (float*)d_out;

    cudaFuncSetAttribute(halo_attn, cudaFuncAttributeMaxDynamicSharedMemorySize,
                         SMEM_BYTES);

    qkv_gemm<<<dim3(SPATIAL / GBN, OQKV / GBM, BATCH), 256>>>(x, qw, kvw);
    halo_attn<<<dim3(NB, BATCH * NUM_HEADS), 128, SMEM_BYTES>>>(hrel, wrel, out);
}